// round 1
// baseline (speedup 1.0000x reference)
#include <cuda_runtime.h>
#include <math.h>

#define N_NODES 50000
#define N_EDGES 800000
#define IN_DIM  256
#define OUT_DIM 64
#define ALPHA   0.2f
#define GAT_EPS 9e-15f

// ---------------- scratch (static device allocations; no cudaMalloc) ----------
__device__ float        g_h[N_NODES * OUT_DIM];       // 12.8 MB
__device__ float        g_s[N_NODES];
__device__ float        g_t[N_NODES];
__device__ float        g_edge_a[N_EDGES];            // leaky-relu'd logits
__device__ int          g_deg[N_NODES];
__device__ int          g_off[N_NODES + 1];
__device__ int          g_cur[N_NODES];
__device__ int          g_csr_dst[N_EDGES];
__device__ float        g_csr_a[N_EDGES];
__device__ unsigned int g_max_u;                      // order-encoded float max

// monotonic float<->uint encoding for atomicMax over signed floats
__device__ __forceinline__ unsigned fenc(float f) {
    unsigned b = __float_as_uint(f);
    return (b & 0x80000000u) ? ~b : (b | 0x80000000u);
}
__device__ __forceinline__ float fdec(unsigned u) {
    unsigned b = (u & 0x80000000u) ? (u & 0x7FFFFFFFu) : ~u;
    return __uint_as_float(b);
}

// ---------------- K0: reset per-launch state (graph replays reuse scratch) ----
__global__ void reset_kernel() {
    int i = blockIdx.x * blockDim.x + threadIdx.x;
    if (i == 0) g_max_u = fenc(-INFINITY);
    for (; i < N_NODES; i += gridDim.x * blockDim.x) g_deg[i] = 0;
}

// ---------------- K1: h = x @ W  (BM=64, BN=64, BK=32, 256 thr, 4x4 microtile)
#define BM 64
#define BN 64
#define BK 32
__global__ void __launch_bounds__(256) gemm_kernel(const float* __restrict__ x,
                                                   const float* __restrict__ W) {
    __shared__ float xs[BK][BM + 1];   // [k][m], padded
    __shared__ float ws[BK][BN];       // [k][n]
    const int tid = threadIdx.x;
    const int tx = tid & 15;           // n-tile coord
    const int ty = tid >> 4;           // m-tile coord
    const int block_row = blockIdx.x * BM;

    float acc[4][4];
#pragma unroll
    for (int i = 0; i < 4; i++)
#pragma unroll
        for (int j = 0; j < 4; j++) acc[i][j] = 0.0f;

    for (int kb = 0; kb < IN_DIM; kb += BK) {
        // stage x tile: 64 rows x 32 k  (2 float4 per thread)
#pragma unroll
        for (int r = 0; r < 2; r++) {
            int m  = r * 32 + (tid >> 3);
            int k4 = (tid & 7) * 4;
            int grow = block_row + m;
            float4 v = make_float4(0.f, 0.f, 0.f, 0.f);
            if (grow < N_NODES)
                v = *reinterpret_cast<const float4*>(&x[(size_t)grow * IN_DIM + kb + k4]);
            xs[k4 + 0][m] = v.x;
            xs[k4 + 1][m] = v.y;
            xs[k4 + 2][m] = v.z;
            xs[k4 + 3][m] = v.w;
        }
        // stage W tile: 32 k x 64 n (2 float4 per thread)
#pragma unroll
        for (int r = 0; r < 2; r++) {
            int k  = r * 16 + (tid >> 4);
            int n4 = (tid & 15) * 4;
            float4 wv = *reinterpret_cast<const float4*>(&W[(size_t)(kb + k) * OUT_DIM + n4]);
            *reinterpret_cast<float4*>(&ws[k][n4]) = wv;
        }
        __syncthreads();

#pragma unroll
        for (int k = 0; k < BK; k++) {
            float a[4], b[4];
#pragma unroll
            for (int i = 0; i < 4; i++) a[i] = xs[k][ty * 4 + i];
#pragma unroll
            for (int j = 0; j < 4; j++) b[j] = ws[k][tx * 4 + j];
#pragma unroll
            for (int i = 0; i < 4; i++)
#pragma unroll
                for (int j = 0; j < 4; j++) acc[i][j] += a[i] * b[j];
        }
        __syncthreads();
    }

#pragma unroll
    for (int i = 0; i < 4; i++) {
        int row = block_row + ty * 4 + i;
        if (row < N_NODES) {
            float4 v = make_float4(acc[i][0], acc[i][1], acc[i][2], acc[i][3]);
            *reinterpret_cast<float4*>(&g_h[(size_t)row * OUT_DIM + tx * 4]) = v;
        }
    }
}

// ---------------- K2: s[i] = h[i]·a_src, t[i] = h[i]·a_dst  (warp per node) ---
__global__ void st_kernel(const float* __restrict__ attn) {
    int gid  = blockIdx.x * blockDim.x + threadIdx.x;
    int node = gid >> 5;
    int lane = gid & 31;
    if (node >= N_NODES) return;
    float h0 = g_h[node * OUT_DIM + lane];
    float h1 = g_h[node * OUT_DIM + 32 + lane];
    float sp = h0 * attn[lane]      + h1 * attn[32 + lane];
    float tp = h0 * attn[64 + lane] + h1 * attn[96 + lane];
#pragma unroll
    for (int o = 16; o; o >>= 1) {
        sp += __shfl_down_sync(0xFFFFFFFFu, sp, o);
        tp += __shfl_down_sync(0xFFFFFFFFu, tp, o);
    }
    if (lane == 0) { g_s[node] = sp; g_t[node] = tp; }
}

// ---------------- K3: edge logits + degree count + global max ----------------
__global__ void edge_kernel(const int* __restrict__ edge) {
    __shared__ float red[256];
    int e = blockIdx.x * blockDim.x + threadIdx.x;
    float a = -INFINITY;
    if (e < N_EDGES) {
        int src = edge[e];
        int dst = edge[N_EDGES + e];
        float v = g_s[src] + g_t[dst];
        a = (v >= 0.0f) ? v : ALPHA * v;
        g_edge_a[e] = a;
        atomicAdd(&g_deg[src], 1);
    }
    red[threadIdx.x] = a;
    __syncthreads();
#pragma unroll
    for (int s = 128; s; s >>= 1) {
        if (threadIdx.x < s) red[threadIdx.x] = fmaxf(red[threadIdx.x], red[threadIdx.x + s]);
        __syncthreads();
    }
    if (threadIdx.x == 0) atomicMax(&g_max_u, fenc(red[0]));
}

// ---------------- K4: single-block exclusive scan over degrees ---------------
__global__ void __launch_bounds__(1024) scan_kernel() {
    __shared__ int ssum[1024];
    const int T = 1024;
    const int chunk = (N_NODES + T - 1) / T;   // 49
    int t = threadIdx.x;
    int beg = t * chunk;
    int end = min(beg + chunk, N_NODES);
    int s = 0;
    for (int i = beg; i < end; i++) s += g_deg[i];
    ssum[t] = s;
    __syncthreads();
    for (int off = 1; off < T; off <<= 1) {
        int v = (t >= off) ? ssum[t - off] : 0;
        __syncthreads();
        ssum[t] += v;
        __syncthreads();
    }
    int run = ssum[t] - s;   // exclusive prefix of this thread's chunk
    for (int i = beg; i < end; i++) {
        g_off[i] = run;
        g_cur[i] = run;
        run += g_deg[i];
    }
    if (beg < N_NODES && end == N_NODES) g_off[N_NODES] = run;
}

// ---------------- K5: CSR fill (counting-sort scatter) -----------------------
__global__ void fill_kernel(const int* __restrict__ edge) {
    int e = blockIdx.x * blockDim.x + threadIdx.x;
    if (e >= N_EDGES) return;
    int src = edge[e];
    int p = atomicAdd(&g_cur[src], 1);
    g_csr_dst[p] = edge[N_EDGES + e];
    g_csr_a[p]   = g_edge_a[e];
}

// ---------------- K6: warp-per-node aggregate (no float atomics) -------------
__global__ void aggr_kernel(float* __restrict__ out) {
    int gid  = blockIdx.x * blockDim.x + threadIdx.x;
    int node = gid >> 5;
    int lane = gid & 31;
    if (node >= N_NODES) return;

    const float M = fdec(g_max_u);
    int beg = g_off[node];
    int end = g_off[node + 1];

    const float2* __restrict__ h2 = reinterpret_cast<const float2*>(g_h);
    float2 acc = make_float2(0.f, 0.f);
    float rs = 0.f;

    for (int j = beg; j < end; j++) {
        int   dst = g_csr_dst[j];
        float a   = g_csr_a[j];
        float ee  = __expf(a - M);
        rs += ee;
        float2 hv = h2[(size_t)dst * 32 + lane];
        acc.x += ee * hv.x;
        acc.y += ee * hv.y;
    }
    float inv = 1.0f / (rs + GAT_EPS);
    reinterpret_cast<float2*>(out)[(size_t)node * 32 + lane] =
        make_float2(acc.x * inv, acc.y * inv);
}

// ---------------- launch ------------------------------------------------------
extern "C" void kernel_launch(void* const* d_in, const int* in_sizes, int n_in,
                              void* d_out, int out_size) {
    const float* x    = (const float*)d_in[0];
    const int*   edge = (const int*)  d_in[1];
    const float* W    = (const float*)d_in[2];
    const float* attn = (const float*)d_in[3];
    float*       out  = (float*)d_out;

    reset_kernel<<<128, 256>>>();
    gemm_kernel<<<(N_NODES + BM - 1) / BM, 256>>>(x, W);
    st_kernel<<<(N_NODES * 32 + 255) / 256, 256>>>(attn);
    edge_kernel<<<(N_EDGES + 255) / 256, 256>>>(edge);
    scan_kernel<<<1, 1024>>>();
    fill_kernel<<<(N_EDGES + 255) / 256, 256>>>(edge);
    aggr_kernel<<<(N_NODES * 32 + 255) / 256, 256>>>(out);
}

// round 2
// speedup vs baseline: 1.0564x; 1.0564x over previous
#include <cuda_runtime.h>
#include <math.h>

#define N_NODES 50000
#define N_EDGES 800000
#define IN_DIM  256
#define OUT_DIM 64
#define ALPHA   0.2f
#define GAT_EPS 9e-15f

// ---------------- scratch ----------------------------------------------------
__device__ float        g_h[N_NODES * OUT_DIM];       // 12.8 MB
__device__ float        g_s[N_NODES];
__device__ float        g_t[N_NODES];
__device__ int          g_deg[N_NODES];
__device__ int          g_off[N_NODES + 1];
__device__ int          g_cur[N_NODES];
__device__ int          g_csr_dst[N_EDGES];
__device__ float        g_csr_a[N_EDGES];
__device__ unsigned int g_max_u;

__device__ __forceinline__ unsigned fenc(float f) {
    unsigned b = __float_as_uint(f);
    return (b & 0x80000000u) ? ~b : (b | 0x80000000u);
}
__device__ __forceinline__ float fdec(unsigned u) {
    unsigned b = (u & 0x80000000u) ? (u & 0x7FFFFFFFu) : ~u;
    return __uint_as_float(b);
}

// ---------------- K0: reset ---------------------------------------------------
__global__ void reset_kernel() {
    int i = blockIdx.x * blockDim.x + threadIdx.x;
    if (i == 0) g_max_u = fenc(-INFINITY);
    for (; i < N_NODES; i += gridDim.x * blockDim.x) g_deg[i] = 0;
}

// ---------------- K1: h = x @ W + fused s,t  (128x64x32, 8x8 microtile) ------
#define GBM 128
#define GBN 64
#define GBK 32
__global__ void __launch_bounds__(128) gemm_kernel(const float* __restrict__ x,
                                                   const float* __restrict__ W,
                                                   const float* __restrict__ attn) {
    __shared__ float xs[GBK][GBM + 4];
    __shared__ float ws[GBK][GBN];
    const int tid = threadIdx.x;
    const int tx = tid >> 3;            // 0..15 : m-tile
    const int ty = tid & 7;             // 0..7  : n-tile
    const int block_row = blockIdx.x * GBM;

    float acc[8][8];
#pragma unroll
    for (int i = 0; i < 8; i++)
#pragma unroll
        for (int j = 0; j < 8; j++) acc[i][j] = 0.0f;

    for (int kb = 0; kb < IN_DIM; kb += GBK) {
        // stage x tile: 128 rows x 32 k = 1024 float4, 8 per thread
#pragma unroll
        for (int r = 0; r < 8; r++) {
            int idx = r * 128 + tid;
            int m   = idx >> 3;
            int k4  = (idx & 7) * 4;
            int grow = block_row + m;
            float4 v = make_float4(0.f, 0.f, 0.f, 0.f);
            if (grow < N_NODES)
                v = *reinterpret_cast<const float4*>(&x[(size_t)grow * IN_DIM + kb + k4]);
            xs[k4 + 0][m] = v.x;
            xs[k4 + 1][m] = v.y;
            xs[k4 + 2][m] = v.z;
            xs[k4 + 3][m] = v.w;
        }
        // stage W tile: 32 k x 64 n = 512 float4, 4 per thread
#pragma unroll
        for (int r = 0; r < 4; r++) {
            int idx = r * 128 + tid;
            int k   = idx >> 4;
            int n4  = (idx & 15) * 4;
            *reinterpret_cast<float4*>(&ws[k][n4]) =
                *reinterpret_cast<const float4*>(&W[(size_t)(kb + k) * OUT_DIM + n4]);
        }
        __syncthreads();

#pragma unroll
        for (int k = 0; k < GBK; k++) {
            float a[8], b[8];
            *reinterpret_cast<float4*>(&a[0]) = *reinterpret_cast<float4*>(&xs[k][tx * 8]);
            *reinterpret_cast<float4*>(&a[4]) = *reinterpret_cast<float4*>(&xs[k][tx * 8 + 4]);
            *reinterpret_cast<float4*>(&b[0]) = *reinterpret_cast<float4*>(&ws[k][ty * 8]);
            *reinterpret_cast<float4*>(&b[4]) = *reinterpret_cast<float4*>(&ws[k][ty * 8 + 4]);
#pragma unroll
            for (int i = 0; i < 8; i++)
#pragma unroll
                for (int j = 0; j < 8; j++) acc[i][j] += a[i] * b[j];
        }
        __syncthreads();
    }

    // store h
#pragma unroll
    for (int i = 0; i < 8; i++) {
        int row = block_row + tx * 8 + i;
        if (row < N_NODES) {
            float4 v0 = make_float4(acc[i][0], acc[i][1], acc[i][2], acc[i][3]);
            float4 v1 = make_float4(acc[i][4], acc[i][5], acc[i][6], acc[i][7]);
            *reinterpret_cast<float4*>(&g_h[(size_t)row * OUT_DIM + ty * 8])     = v0;
            *reinterpret_cast<float4*>(&g_h[(size_t)row * OUT_DIM + ty * 8 + 4]) = v1;
        }
    }

    // fused s,t epilogue: s[row] = h[row]·attn[0:64], t[row] = h[row]·attn[64:128]
    float as[8], ad[8];
#pragma unroll
    for (int j = 0; j < 8; j++) {
        as[j] = attn[ty * 8 + j];
        ad[j] = attn[64 + ty * 8 + j];
    }
#pragma unroll
    for (int i = 0; i < 8; i++) {
        float sp = 0.f, tp = 0.f;
#pragma unroll
        for (int j = 0; j < 8; j++) {
            sp = fmaf(acc[i][j], as[j], sp);
            tp = fmaf(acc[i][j], ad[j], tp);
        }
        // reduce over ty (lanes within 8-lane groups share tx)
#pragma unroll
        for (int o = 4; o; o >>= 1) {
            sp += __shfl_xor_sync(0xFFFFFFFFu, sp, o);
            tp += __shfl_xor_sync(0xFFFFFFFFu, tp, o);
        }
        if (ty == 0) {
            int row = block_row + tx * 8 + i;
            if (row < N_NODES) { g_s[row] = sp; g_t[row] = tp; }
        }
    }
}

// ---------------- K2: degree count -------------------------------------------
__global__ void deg_kernel(const int* __restrict__ edge) {
    int e = blockIdx.x * blockDim.x + threadIdx.x;
    if (e < N_EDGES) atomicAdd(&g_deg[edge[e]], 1);
}

// ---------------- K3: single-block exclusive scan ----------------------------
__global__ void __launch_bounds__(1024) scan_kernel() {
    __shared__ int ssum[1024];
    const int T = 1024;
    const int chunk = (N_NODES + T - 1) / T;
    int t = threadIdx.x;
    int beg = t * chunk;
    int end = min(beg + chunk, N_NODES);
    int s = 0;
    for (int i = beg; i < end; i++) s += g_deg[i];
    ssum[t] = s;
    __syncthreads();
    for (int off = 1; off < T; off <<= 1) {
        int v = (t >= off) ? ssum[t - off] : 0;
        __syncthreads();
        ssum[t] += v;
        __syncthreads();
    }
    int run = ssum[t] - s;
    for (int i = beg; i < end; i++) {
        g_off[i] = run;
        g_cur[i] = run;
        run += g_deg[i];
    }
    if (beg < N_NODES && end == N_NODES) g_off[N_NODES] = run;
}

// ---------------- K4: CSR fill + logits + global max -------------------------
__global__ void fill_kernel(const int* __restrict__ edge) {
    __shared__ float red[8];
    int e = blockIdx.x * blockDim.x + threadIdx.x;
    float a = -INFINITY;
    if (e < N_EDGES) {
        int src = edge[e];
        int dst = edge[N_EDGES + e];
        float v = g_s[src] + g_t[dst];
        a = (v >= 0.0f) ? v : ALPHA * v;
        int p = atomicAdd(&g_cur[src], 1);
        g_csr_dst[p] = dst;
        g_csr_a[p]   = a;
    }
    // warp max -> block max -> global atomicMax
    float m = a;
#pragma unroll
    for (int o = 16; o; o >>= 1) m = fmaxf(m, __shfl_xor_sync(0xFFFFFFFFu, m, o));
    if ((threadIdx.x & 31) == 0) red[threadIdx.x >> 5] = m;
    __syncthreads();
    if (threadIdx.x == 0) {
        float bm = red[0];
#pragma unroll
        for (int w = 1; w < 8; w++) bm = fmaxf(bm, red[w]);
        atomicMax(&g_max_u, fenc(bm));
    }
}

// ---------------- K5: warp-per-node aggregate, unroll 4 ----------------------
__global__ void aggr_kernel(float* __restrict__ out) {
    int gid  = blockIdx.x * blockDim.x + threadIdx.x;
    int node = gid >> 5;
    int lane = gid & 31;
    if (node >= N_NODES) return;

    const float M = fdec(g_max_u);
    int beg = g_off[node];
    int end = g_off[node + 1];

    const float2* __restrict__ h2 = reinterpret_cast<const float2*>(g_h);
    float ax = 0.f, ay = 0.f;
    float rs = 0.f;

    int j = beg;
    for (; j + 4 <= end; j += 4) {
        int   d0 = g_csr_dst[j + 0], d1 = g_csr_dst[j + 1];
        int   d2 = g_csr_dst[j + 2], d3 = g_csr_dst[j + 3];
        float a0 = g_csr_a[j + 0],   a1 = g_csr_a[j + 1];
        float a2 = g_csr_a[j + 2],   a3 = g_csr_a[j + 3];
        float e0 = __expf(a0 - M), e1 = __expf(a1 - M);
        float e2 = __expf(a2 - M), e3 = __expf(a3 - M);
        rs += (e0 + e1) + (e2 + e3);
        float2 v0 = h2[(size_t)d0 * 32 + lane];
        float2 v1 = h2[(size_t)d1 * 32 + lane];
        float2 v2 = h2[(size_t)d2 * 32 + lane];
        float2 v3 = h2[(size_t)d3 * 32 + lane];
        ax = fmaf(e0, v0.x, ax); ay = fmaf(e0, v0.y, ay);
        ax = fmaf(e1, v1.x, ax); ay = fmaf(e1, v1.y, ay);
        ax = fmaf(e2, v2.x, ax); ay = fmaf(e2, v2.y, ay);
        ax = fmaf(e3, v3.x, ax); ay = fmaf(e3, v3.y, ay);
    }
    for (; j < end; j++) {
        int   d = g_csr_dst[j];
        float e = __expf(g_csr_a[j] - M);
        rs += e;
        float2 v = h2[(size_t)d * 32 + lane];
        ax = fmaf(e, v.x, ax); ay = fmaf(e, v.y, ay);
    }
    float inv = 1.0f / (rs + GAT_EPS);
    reinterpret_cast<float2*>(out)[(size_t)node * 32 + lane] =
        make_float2(ax * inv, ay * inv);
}

// ---------------- launch ------------------------------------------------------
extern "C" void kernel_launch(void* const* d_in, const int* in_sizes, int n_in,
                              void* d_out, int out_size) {
    const float* x    = (const float*)d_in[0];
    const int*   edge = (const int*)  d_in[1];
    const float* W    = (const float*)d_in[2];
    const float* attn = (const float*)d_in[3];
    float*       out  = (float*)d_out;

    reset_kernel<<<128, 256>>>();
    gemm_kernel<<<(N_NODES + GBM - 1) / GBM, 128>>>(x, W, attn);
    deg_kernel<<<(N_EDGES + 255) / 256, 256>>>(edge);
    scan_kernel<<<1, 1024>>>();
    fill_kernel<<<(N_EDGES + 255) / 256, 256>>>(edge);
    aggr_kernel<<<(N_NODES * 32 + 255) / 256, 256>>>(out);
}

// round 3
// speedup vs baseline: 1.7291x; 1.6368x over previous
#include <cuda_runtime.h>
#include <math.h>

#define N_NODES 50000
#define N_EDGES 800000
#define IN_DIM  256
#define OUT_DIM 64
#define ALPHA   0.2f
#define GAT_EPS 9e-15f

#define SB 256
#define SCAN_NB ((N_NODES + SB - 1) / SB)   // 196

// ---------------- scratch ----------------------------------------------------
__device__ float        g_h[N_NODES * OUT_DIM];       // 12.8 MB
__device__ float        g_s[N_NODES];
__device__ float        g_t[N_NODES];
__device__ int          g_deg[N_NODES];
__device__ int          g_off[N_NODES + 1];
__device__ int          g_cur[N_NODES];
__device__ int          g_bsum[SCAN_NB];
__device__ int          g_csr_dst[N_EDGES];
__device__ float        g_csr_a[N_EDGES];
__device__ unsigned int g_max_u;

__device__ __forceinline__ unsigned fenc(float f) {
    unsigned b = __float_as_uint(f);
    return (b & 0x80000000u) ? ~b : (b | 0x80000000u);
}
__device__ __forceinline__ float fdec(unsigned u) {
    unsigned b = (u & 0x80000000u) ? (u & 0x7FFFFFFFu) : ~u;
    return __uint_as_float(b);
}

// block-wide exclusive scan over 256 threads (warp shfl + warp-total pass)
__device__ __forceinline__ int block_excl_scan_256(int v) {
    __shared__ int wt[8];
    const int tid  = threadIdx.x;
    const int lane = tid & 31;
    const int wid  = tid >> 5;
    int inc = v;
#pragma unroll
    for (int o = 1; o < 32; o <<= 1) {
        int y = __shfl_up_sync(0xFFFFFFFFu, inc, o);
        if (lane >= o) inc += y;
    }
    if (lane == 31) wt[wid] = inc;
    __syncthreads();
    if (tid == 0) {
        int r = 0;
#pragma unroll
        for (int w = 0; w < 8; w++) { int t = wt[w]; wt[w] = r; r += t; }
    }
    __syncthreads();
    return inc - v + wt[wid];
}

// ---------------- K0: reset ---------------------------------------------------
__global__ void reset_kernel() {
    int i = blockIdx.x * blockDim.x + threadIdx.x;
    if (i == 0) { g_max_u = fenc(-INFINITY); g_off[N_NODES] = N_EDGES; }
    for (; i < N_NODES; i += gridDim.x * blockDim.x) g_deg[i] = 0;
}

// ---------------- K1: h = x @ W + fused s,t  (128x64x32, 8x8 microtile) ------
#define GBM 128
#define GBN 64
#define GBK 32
__global__ void __launch_bounds__(128) gemm_kernel(const float* __restrict__ x,
                                                   const float* __restrict__ W,
                                                   const float* __restrict__ attn) {
    __shared__ float xs[GBK][GBM + 4];
    __shared__ float ws[GBK][GBN];
    const int tid = threadIdx.x;
    const int tx = tid >> 3;            // 0..15 : m-tile
    const int ty = tid & 7;             // 0..7  : n-tile
    const int block_row = blockIdx.x * GBM;

    float acc[8][8];
#pragma unroll
    for (int i = 0; i < 8; i++)
#pragma unroll
        for (int j = 0; j < 8; j++) acc[i][j] = 0.0f;

    for (int kb = 0; kb < IN_DIM; kb += GBK) {
#pragma unroll
        for (int r = 0; r < 8; r++) {
            int idx = r * 128 + tid;
            int m   = idx >> 3;
            int k4  = (idx & 7) * 4;
            int grow = block_row + m;
            float4 v = make_float4(0.f, 0.f, 0.f, 0.f);
            if (grow < N_NODES)
                v = *reinterpret_cast<const float4*>(&x[(size_t)grow * IN_DIM + kb + k4]);
            xs[k4 + 0][m] = v.x;
            xs[k4 + 1][m] = v.y;
            xs[k4 + 2][m] = v.z;
            xs[k4 + 3][m] = v.w;
        }
#pragma unroll
        for (int r = 0; r < 4; r++) {
            int idx = r * 128 + tid;
            int k   = idx >> 4;
            int n4  = (idx & 15) * 4;
            *reinterpret_cast<float4*>(&ws[k][n4]) =
                *reinterpret_cast<const float4*>(&W[(size_t)(kb + k) * OUT_DIM + n4]);
        }
        __syncthreads();

#pragma unroll
        for (int k = 0; k < GBK; k++) {
            float a[8], b[8];
            *reinterpret_cast<float4*>(&a[0]) = *reinterpret_cast<float4*>(&xs[k][tx * 8]);
            *reinterpret_cast<float4*>(&a[4]) = *reinterpret_cast<float4*>(&xs[k][tx * 8 + 4]);
            *reinterpret_cast<float4*>(&b[0]) = *reinterpret_cast<float4*>(&ws[k][ty * 8]);
            *reinterpret_cast<float4*>(&b[4]) = *reinterpret_cast<float4*>(&ws[k][ty * 8 + 4]);
#pragma unroll
            for (int i = 0; i < 8; i++)
#pragma unroll
                for (int j = 0; j < 8; j++) acc[i][j] += a[i] * b[j];
        }
        __syncthreads();
    }

#pragma unroll
    for (int i = 0; i < 8; i++) {
        int row = block_row + tx * 8 + i;
        if (row < N_NODES) {
            float4 v0 = make_float4(acc[i][0], acc[i][1], acc[i][2], acc[i][3]);
            float4 v1 = make_float4(acc[i][4], acc[i][5], acc[i][6], acc[i][7]);
            *reinterpret_cast<float4*>(&g_h[(size_t)row * OUT_DIM + ty * 8])     = v0;
            *reinterpret_cast<float4*>(&g_h[(size_t)row * OUT_DIM + ty * 8 + 4]) = v1;
        }
    }

    float as[8], ad[8];
#pragma unroll
    for (int j = 0; j < 8; j++) {
        as[j] = attn[ty * 8 + j];
        ad[j] = attn[64 + ty * 8 + j];
    }
#pragma unroll
    for (int i = 0; i < 8; i++) {
        float sp = 0.f, tp = 0.f;
#pragma unroll
        for (int j = 0; j < 8; j++) {
            sp = fmaf(acc[i][j], as[j], sp);
            tp = fmaf(acc[i][j], ad[j], tp);
        }
#pragma unroll
        for (int o = 4; o; o >>= 1) {
            sp += __shfl_xor_sync(0xFFFFFFFFu, sp, o);
            tp += __shfl_xor_sync(0xFFFFFFFFu, tp, o);
        }
        if (ty == 0) {
            int row = block_row + tx * 8 + i;
            if (row < N_NODES) { g_s[row] = sp; g_t[row] = tp; }
        }
    }
}

// ---------------- K2: degree count -------------------------------------------
__global__ void deg_kernel(const int* __restrict__ edge) {
    int e = blockIdx.x * blockDim.x + threadIdx.x;
    if (e < N_EDGES) atomicAdd(&g_deg[edge[e]], 1);
}

// ---------------- K3a/b/c: parallel exclusive scan ---------------------------
__global__ void __launch_bounds__(SB) scanA_kernel() {
    int i = blockIdx.x * SB + threadIdx.x;
    int v = (i < N_NODES) ? g_deg[i] : 0;
    int ex = block_excl_scan_256(v);
    if (i < N_NODES) g_off[i] = ex;
    if (threadIdx.x == SB - 1) g_bsum[blockIdx.x] = ex + v;
}

__global__ void __launch_bounds__(SB) scanB_kernel() {
    int t = threadIdx.x;
    int v = (t < SCAN_NB) ? g_bsum[t] : 0;
    int ex = block_excl_scan_256(v);
    if (t < SCAN_NB) g_bsum[t] = ex;
}

__global__ void __launch_bounds__(SB) scanC_kernel() {
    int i = blockIdx.x * SB + threadIdx.x;
    if (i < N_NODES) {
        int o = g_off[i] + g_bsum[blockIdx.x];
        g_off[i] = o;
        g_cur[i] = o;
    }
}

// ---------------- K4: CSR fill + logits + global max -------------------------
__global__ void fill_kernel(const int* __restrict__ edge) {
    __shared__ float red[8];
    int e = blockIdx.x * blockDim.x + threadIdx.x;
    float a = -INFINITY;
    if (e < N_EDGES) {
        int src = edge[e];
        int dst = edge[N_EDGES + e];
        float v = g_s[src] + g_t[dst];
        a = (v >= 0.0f) ? v : ALPHA * v;
        int p = atomicAdd(&g_cur[src], 1);
        g_csr_dst[p] = dst;
        g_csr_a[p]   = a;
    }
    float m = a;
#pragma unroll
    for (int o = 16; o; o >>= 1) m = fmaxf(m, __shfl_xor_sync(0xFFFFFFFFu, m, o));
    if ((threadIdx.x & 31) == 0) red[threadIdx.x >> 5] = m;
    __syncthreads();
    if (threadIdx.x == 0) {
        float bm = red[0];
#pragma unroll
        for (int w = 1; w < 8; w++) bm = fmaxf(bm, red[w]);
        atomicMax(&g_max_u, fenc(bm));
    }
}

// ---------------- K5: warp-per-node aggregate, unroll 4 ----------------------
__global__ void aggr_kernel(float* __restrict__ out) {
    int gid  = blockIdx.x * blockDim.x + threadIdx.x;
    int node = gid >> 5;
    int lane = gid & 31;
    if (node >= N_NODES) return;

    const float M = fdec(g_max_u);
    int beg = g_off[node];
    int end = g_off[node + 1];

    const float2* __restrict__ h2 = reinterpret_cast<const float2*>(g_h);
    float ax = 0.f, ay = 0.f;
    float rs = 0.f;

    int j = beg;
    for (; j + 4 <= end; j += 4) {
        int   d0 = g_csr_dst[j + 0], d1 = g_csr_dst[j + 1];
        int   d2 = g_csr_dst[j + 2], d3 = g_csr_dst[j + 3];
        float a0 = g_csr_a[j + 0],   a1 = g_csr_a[j + 1];
        float a2 = g_csr_a[j + 2],   a3 = g_csr_a[j + 3];
        float e0 = __expf(a0 - M), e1 = __expf(a1 - M);
        float e2 = __expf(a2 - M), e3 = __expf(a3 - M);
        rs += (e0 + e1) + (e2 + e3);
        float2 v0 = h2[(size_t)d0 * 32 + lane];
        float2 v1 = h2[(size_t)d1 * 32 + lane];
        float2 v2 = h2[(size_t)d2 * 32 + lane];
        float2 v3 = h2[(size_t)d3 * 32 + lane];
        ax = fmaf(e0, v0.x, ax); ay = fmaf(e0, v0.y, ay);
        ax = fmaf(e1, v1.x, ax); ay = fmaf(e1, v1.y, ay);
        ax = fmaf(e2, v2.x, ax); ay = fmaf(e2, v2.y, ay);
        ax = fmaf(e3, v3.x, ax); ay = fmaf(e3, v3.y, ay);
    }
    for (; j < end; j++) {
        int   d = g_csr_dst[j];
        float e = __expf(g_csr_a[j] - M);
        rs += e;
        float2 v = h2[(size_t)d * 32 + lane];
        ax = fmaf(e, v.x, ax); ay = fmaf(e, v.y, ay);
    }
    float inv = 1.0f / (rs + GAT_EPS);
    reinterpret_cast<float2*>(out)[(size_t)node * 32 + lane] =
        make_float2(ax * inv, ay * inv);
}

// ---------------- launch ------------------------------------------------------
extern "C" void kernel_launch(void* const* d_in, const int* in_sizes, int n_in,
                              void* d_out, int out_size) {
    const float* x    = (const float*)d_in[0];
    const int*   edge = (const int*)  d_in[1];
    const float* W    = (const float*)d_in[2];
    const float* attn = (const float*)d_in[3];
    float*       out  = (float*)d_out;

    reset_kernel<<<128, 256>>>();
    gemm_kernel<<<(N_NODES + GBM - 1) / GBM, 128>>>(x, W, attn);
    deg_kernel<<<(N_EDGES + 255) / 256, 256>>>(edge);
    scanA_kernel<<<SCAN_NB, SB>>>();
    scanB_kernel<<<1, SB>>>();
    scanC_kernel<<<SCAN_NB, SB>>>();
    fill_kernel<<<(N_EDGES + 255) / 256, 256>>>(edge);
    aggr_kernel<<<(N_NODES * 32 + 255) / 256, 256>>>(out);
}